// round 1
// baseline (speedup 1.0000x reference)
#include <cuda_runtime.h>
#include <math.h>
#include <stdint.h>

// ---------------- problem constants ----------------
#define BATCH    2
#define SEQLEN   1024
#define DMODEL   1024
#define DINNER   2048
#define NHEADS   32
#define HEADDIM  64
#define DSTATE   128
#define DCONV    4
#define CONVDIM  2304          // DINNER + 2*DSTATE
#define DINPROJ  4384          // 2*DINNER + 2*DSTATE + NHEADS
#define ROWS     (BATCH*SEQLEN)   // 2048
#define EPS      1e-5f

// ---------------- scratch (static device allocations only) ----------------
__device__ float g_zx [ROWS*DINPROJ];   // in-proj output  (z | xBC | dt)
__device__ float g_xbc[ROWS*CONVDIM];   // conv+SiLU output (xs | B | C)
__device__ float g_dt [ROWS*NHEADS];
__device__ float g_dA [ROWS*NHEADS];
__device__ float g_yp0[ROWS*DINNER];    // scan partial (n in [0,64))
__device__ float g_yp1[ROWS*DINNER];    // scan partial (n in [64,128))
__device__ float g_yn [ROWS*DINNER];    // normalized gated y

// ---------------- packed f32x2 helpers (sm_100+) ----------------
__device__ __forceinline__ float2 ffma2(float2 a, float2 b, float2 c) {
    float2 d;
    asm("fma.rn.f32x2 %0, %1, %2, %3;"
        : "=l"(reinterpret_cast<unsigned long long &>(d))
        : "l"(reinterpret_cast<const unsigned long long &>(a)),
          "l"(reinterpret_cast<const unsigned long long &>(b)),
          "l"(reinterpret_cast<const unsigned long long &>(c)));
    return d;
}
__device__ __forceinline__ float2 fmul2(float2 a, float2 b) {
    float2 d;
    asm("mul.rn.f32x2 %0, %1, %2;"
        : "=l"(reinterpret_cast<unsigned long long &>(d))
        : "l"(reinterpret_cast<const unsigned long long &>(a)),
          "l"(reinterpret_cast<const unsigned long long &>(b)));
    return d;
}

// =====================================================================
// GEMM: C[M,N] = A[M,K] * W[N,K]^T  (+ optional residual), fp32, packed f32x2
// Tile 128(M) x 64(N) x 16(K), 256 threads, each thread 8x4 outputs (as 8x2 float2)
// =====================================================================
template<bool RES>
__global__ __launch_bounds__(256)
void gemm_nt(const float* __restrict__ A, const float* __restrict__ W,
             const float* __restrict__ resid, float* __restrict__ C,
             int M, int N, int K)
{
    __shared__ __align__(16) float2 As[16][128];   // A duplicated (a,a)
    __shared__ __align__(16) float  Ws[16][64];

    const int tid = threadIdx.x;
    const int tx  = tid & 15;          // 16 col groups of 4
    const int ty  = tid >> 4;          // 16 row groups of 8
    const int row0 = blockIdx.y * 128;
    const int col0 = blockIdx.x * 64;

    float2 acc[8][2];
#pragma unroll
    for (int i = 0; i < 8; i++) { acc[i][0] = make_float2(0.f,0.f); acc[i][1] = make_float2(0.f,0.f); }

    for (int k0 = 0; k0 < K; k0 += 16) {
        // load A tile: 128x16 floats = 512 float4, 2 per thread
#pragma unroll
        for (int it = 0; it < 2; it++) {
            int idx = tid + it*256;
            int m  = idx >> 2;
            int k4 = idx & 3;
            float4 av = *reinterpret_cast<const float4*>(&A[(size_t)(row0+m)*K + k0 + k4*4]);
            As[k4*4+0][m] = make_float2(av.x, av.x);
            As[k4*4+1][m] = make_float2(av.y, av.y);
            As[k4*4+2][m] = make_float2(av.z, av.z);
            As[k4*4+3][m] = make_float2(av.w, av.w);
        }
        // load W tile: 64x16 floats = 256 float4, 1 per thread (guard N)
        {
            int m  = tid >> 2;
            int k4 = tid & 3;
            float4 wv = make_float4(0.f,0.f,0.f,0.f);
            if (col0 + m < N)
                wv = *reinterpret_cast<const float4*>(&W[(size_t)(col0+m)*K + k0 + k4*4]);
            Ws[k4*4+0][m] = wv.x;
            Ws[k4*4+1][m] = wv.y;
            Ws[k4*4+2][m] = wv.z;
            Ws[k4*4+3][m] = wv.w;
        }
        __syncthreads();
#pragma unroll
        for (int kk = 0; kk < 16; kk++) {
            float2 a[8];
#pragma unroll
            for (int i = 0; i < 8; i++) a[i] = As[kk][ty*8+i];
            float4 bv = *reinterpret_cast<const float4*>(&Ws[kk][tx*4]);
            float2 b0 = make_float2(bv.x, bv.y);
            float2 b1 = make_float2(bv.z, bv.w);
#pragma unroll
            for (int i = 0; i < 8; i++) {
                acc[i][0] = ffma2(a[i], b0, acc[i][0]);
                acc[i][1] = ffma2(a[i], b1, acc[i][1]);
            }
        }
        __syncthreads();
    }

#pragma unroll
    for (int i = 0; i < 8; i++) {
        int row = row0 + ty*8 + i;
#pragma unroll
        for (int jj = 0; jj < 2; jj++) {
            int col = col0 + tx*4 + jj*2;
            if (col < N) {
                float2 v = acc[i][jj];
                if (RES) v.x += resid[(size_t)row*N + col];
                C[(size_t)row*N + col] = v.x;
                if (col + 1 < N) {
                    float v1 = v.y;
                    if (RES) v1 += resid[(size_t)row*N + col + 1];
                    C[(size_t)row*N + col + 1] = v1;
                }
            }
        }
    }
}

// =====================================================================
// Causal depthwise conv (width 4) + bias + SiLU on xBC; also dt/dA precompute
// =====================================================================
__global__ __launch_bounds__(256)
void conv_act_kernel(const float* __restrict__ conv_w, const float* __restrict__ conv_b,
                     const float* __restrict__ dt_bias, const float* __restrict__ A_log)
{
    const int c = blockIdx.x*256 + threadIdx.x;
    const int t = blockIdx.y;
    const int b = blockIdx.z;
    const size_t row = (size_t)b*SEQLEN + t;

    if (c < CONVDIM) {
        float acc = conv_b[c];
#pragma unroll
        for (int k = 0; k < DCONV; k++) {
            int tt = t - (DCONV-1) + k;
            if (tt >= 0)
                acc += g_zx[((size_t)b*SEQLEN + tt)*DINPROJ + DINNER + c] * conv_w[c*DCONV + k];
        }
        // SiLU
        g_xbc[row*CONVDIM + c] = acc / (1.f + expf(-acc));
    }
    if (blockIdx.x == 0 && threadIdx.x < NHEADS) {
        int h = threadIdx.x;
        float raw = g_zx[row*DINPROJ + (DINNER + CONVDIM) + h] + dt_bias[h];
        float dtv = (raw > 20.f) ? raw : log1pf(expf(raw));
        g_dt[row*NHEADS + h] = dtv;
        g_dA[row*NHEADS + h] = expf(dtv * (-expf(A_log[h])));
    }
}

// =====================================================================
// Selective scan. grid = (NHEADS, BATCH, 2 n-halves) = 128 blocks (1 per SM).
// 256 threads: p = tid>>2 in [0,64), ns = tid&3; each thread owns 8 float2
// state pairs at n = nbase + ns*2 + j*8 (+{0,1}) -> conflict-free LDS.64.
// y reduced over the 4 ns lanes via shfl, written to per-half partial buffer.
// =====================================================================
__global__ __launch_bounds__(256)
void scan_kernel()
{
    const int h    = blockIdx.x;
    const int b    = blockIdx.y;
    const int half = blockIdx.z;
    const int tid  = threadIdx.x;
    const int p    = tid >> 2;
    const int ns   = tid & 3;
    const int nbase = half * 64;
    float* __restrict__ yout = half ? g_yp1 : g_yp0;

    __shared__ __align__(16) float sB[8][64];
    __shared__ __align__(16) float sC[8][64];
    __shared__ __align__(16) float sX[8][64];
    __shared__ float sdA[8];
    __shared__ float sdt[8];

    float2 hs[8];
#pragma unroll
    for (int j = 0; j < 8; j++) hs[j] = make_float2(0.f, 0.f);

    for (int t0 = 0; t0 < SEQLEN; t0 += 8) {
        __syncthreads();
        // stage 8 steps of B, C, x(head slice), dA, dt
#pragma unroll
        for (int it = 0; it < 2; it++) {
            int idx = tid + it*256;
            int s = idx >> 6, i = idx & 63;
            size_t row = ((size_t)b*SEQLEN + t0 + s)*CONVDIM;
            sB[s][i] = g_xbc[row + DINNER + nbase + i];
            sC[s][i] = g_xbc[row + DINNER + DSTATE + nbase + i];
            sX[s][i] = g_xbc[row + h*HEADDIM + i];
        }
        if (tid < 16) {
            int s = tid & 7;
            size_t r = ((size_t)b*SEQLEN + t0 + s)*NHEADS + h;
            if (tid < 8) sdA[s] = g_dA[r];
            else         sdt[s] = g_dt[r];
        }
        __syncthreads();

#pragma unroll
        for (int s = 0; s < 8; s++) {
            float dAv = sdA[s];
            float2 dA2 = make_float2(dAv, dAv);
            float coef = sdt[s] * sX[s][p];
            float2 c2  = make_float2(coef, coef);
            float2 acc = make_float2(0.f, 0.f);
#pragma unroll
            for (int j = 0; j < 8; j++) {
                int no = ns*2 + j*8;
                float2 Bj = *reinterpret_cast<const float2*>(&sB[s][no]);
                float2 Cj = *reinterpret_cast<const float2*>(&sC[s][no]);
                hs[j] = ffma2(hs[j], dA2, fmul2(c2, Bj));   // h = h*dA + (dt*x_p)*B_n
                acc   = ffma2(hs[j], Cj, acc);              // y += h*C_n
            }
            float y = acc.x + acc.y;
            y += __shfl_down_sync(0xffffffffu, y, 2, 4);
            y += __shfl_down_sync(0xffffffffu, y, 1, 4);
            if (ns == 0)
                yout[((size_t)b*SEQLEN + t0 + s)*DINNER + h*HEADDIM + p] = y;
        }
    }
}

// =====================================================================
// y = (yp0 + yp1 + D[h]*xs) * silu(z); RMSNorm over DINNER; * norm_w
// one block per (b,t) row
// =====================================================================
__global__ __launch_bounds__(256)
void gate_norm_kernel(const float* __restrict__ Dw, const float* __restrict__ norm_w)
{
    const int t = blockIdx.x;
    const int b = blockIdx.y;
    const size_t row = (size_t)b*SEQLEN + t;
    const float* __restrict__ zrow = &g_zx [row*DINPROJ];
    const float* __restrict__ xrow = &g_xbc[row*CONVDIM];
    const float* __restrict__ y0   = &g_yp0[row*DINNER];
    const float* __restrict__ y1   = &g_yp1[row*DINNER];

    float vals[8];
    float ss = 0.f;
#pragma unroll
    for (int r = 0; r < 8; r++) {
        int c = r*256 + threadIdx.x;
        int hh = c >> 6;
        float v = y0[c] + y1[c] + Dw[hh]*xrow[c];
        float z = zrow[c];
        v *= z / (1.f + expf(-z));
        vals[r] = v;
        ss += v*v;
    }
    __shared__ float red[256];
    red[threadIdx.x] = ss;
    __syncthreads();
    for (int off = 128; off > 0; off >>= 1) {
        if (threadIdx.x < off) red[threadIdx.x] += red[threadIdx.x + off];
        __syncthreads();
    }
    float scale = rsqrtf(red[0]/(float)DINNER + EPS);
#pragma unroll
    for (int r = 0; r < 8; r++) {
        int c = r*256 + threadIdx.x;
        g_yn[row*DINNER + c] = vals[r]*scale*norm_w[c];
    }
}

// =====================================================================
extern "C" void kernel_launch(void* const* d_in, const int* in_sizes, int n_in,
                              void* d_out, int out_size)
{
    const float* x          = (const float*)d_in[0];
    const float* in_proj_w  = (const float*)d_in[1];
    const float* conv_w     = (const float*)d_in[2];
    const float* conv_b     = (const float*)d_in[3];
    const float* dt_bias    = (const float*)d_in[4];
    const float* A_log      = (const float*)d_in[5];
    const float* Dw         = (const float*)d_in[6];
    const float* norm_w     = (const float*)d_in[7];
    const float* out_proj_w = (const float*)d_in[8];
    float* out = (float*)d_out;

    float *p_zx = nullptr, *p_yn = nullptr;
    cudaGetSymbolAddress((void**)&p_zx, g_zx);
    cudaGetSymbolAddress((void**)&p_yn, g_yn);

    // 1) zxbcdt = x @ in_proj_w^T        [2048 x 4384]
    gemm_nt<false><<<dim3((DINPROJ + 63)/64, ROWS/128), 256>>>(
        x, in_proj_w, nullptr, p_zx, ROWS, DINPROJ, DMODEL);

    // 2) causal depthwise conv + SiLU; dt softplus; dA
    conv_act_kernel<<<dim3(CONVDIM/256, SEQLEN, BATCH), 256>>>(
        conv_w, conv_b, dt_bias, A_log);

    // 3) selective scan -> two n-half partial y buffers
    scan_kernel<<<dim3(NHEADS, BATCH, 2), 256>>>();

    // 4) skip + gate + RMSNorm
    gate_norm_kernel<<<dim3(SEQLEN, BATCH), 256>>>(Dw, norm_w);

    // 5) out = x + yn @ out_proj_w^T     [2048 x 1024]
    gemm_nt<true><<<dim3(DMODEL/64, ROWS/128), 256>>>(
        p_yn, out_proj_w, x, out, ROWS, DMODEL, DINNER);
}

// round 3
// speedup vs baseline: 2.3050x; 2.3050x over previous
#include <cuda_runtime.h>
#include <cuda_bf16.h>
#include <math.h>
#include <stdint.h>

// ---------------- problem constants ----------------
#define BATCH    2
#define SEQLEN   1024
#define DMODEL   1024
#define DINNER   2048
#define NHEADS   32
#define HEADDIM  64
#define DSTATE   128
#define DCONV    4
#define CONVDIM  2304          // DINNER + 2*DSTATE
#define DINPROJ  4384          // 2*DINNER + 2*DSTATE + NHEADS
#define ROWS     (BATCH*SEQLEN)   // 2048
#define EPS      1e-5f

// ---------------- scratch (static device allocations only) ----------------
__device__ __align__(1024) float g_zx [ROWS*DINPROJ];
__device__ __align__(1024) float g_xbc[ROWS*CONVDIM];
__device__ __align__(1024) float g_dt [ROWS*NHEADS];
__device__ __align__(1024) float g_dA [ROWS*NHEADS];
__device__ __align__(1024) float g_yp0[ROWS*DINNER];
__device__ __align__(1024) float g_yp1[ROWS*DINNER];
__device__ __align__(1024) __nv_bfloat16 g_xh [ROWS*DMODEL];
__device__ __align__(1024) __nv_bfloat16 g_xl [ROWS*DMODEL];
__device__ __align__(1024) __nv_bfloat16 g_w1h[DINPROJ*DMODEL];
__device__ __align__(1024) __nv_bfloat16 g_w1l[DINPROJ*DMODEL];
__device__ __align__(1024) __nv_bfloat16 g_w2h[DMODEL*DINNER];
__device__ __align__(1024) __nv_bfloat16 g_w2l[DMODEL*DINNER];
__device__ __align__(1024) __nv_bfloat16 g_ynh[ROWS*DINNER];
__device__ __align__(1024) __nv_bfloat16 g_ynl[ROWS*DINNER];

// ---------------- packed f32x2 helpers ----------------
__device__ __forceinline__ float2 ffma2(float2 a, float2 b, float2 c) {
    float2 d;
    asm("fma.rn.f32x2 %0, %1, %2, %3;"
        : "=l"(reinterpret_cast<unsigned long long &>(d))
        : "l"(reinterpret_cast<const unsigned long long &>(a)),
          "l"(reinterpret_cast<const unsigned long long &>(b)),
          "l"(reinterpret_cast<const unsigned long long &>(c)));
    return d;
}
__device__ __forceinline__ float2 fmul2(float2 a, float2 b) {
    float2 d;
    asm("mul.rn.f32x2 %0, %1, %2;"
        : "=l"(reinterpret_cast<unsigned long long &>(d))
        : "l"(reinterpret_cast<const unsigned long long &>(a)),
          "l"(reinterpret_cast<const unsigned long long &>(b)));
    return d;
}

// ---------------- sm_80-era primitives (compile for plain sm_103) ----------
__device__ __forceinline__ uint32_t smem_u32(const void* p) {
    uint32_t a;
    asm("{ .reg .u64 t; cvta.to.shared.u64 t, %1; cvt.u32.u64 %0, t; }" : "=r"(a) : "l"(p));
    return a;
}
__device__ __forceinline__ void cp16(uint32_t dst, const void* src) {
    asm volatile("cp.async.cg.shared.global [%0], [%1], 16;" :: "r"(dst), "l"(src));
}
__device__ __forceinline__ void cp_commit() { asm volatile("cp.async.commit_group;" ::: "memory"); }
template<int W> __device__ __forceinline__ void cp_wait() {
    asm volatile("cp.async.wait_group %0;" :: "n"(W) : "memory");
}
__device__ __forceinline__ void ldsm_x4(uint32_t& r0, uint32_t& r1, uint32_t& r2, uint32_t& r3, uint32_t a) {
    asm volatile("ldmatrix.sync.aligned.m8n8.x4.shared.b16 {%0,%1,%2,%3}, [%4];"
                 : "=r"(r0), "=r"(r1), "=r"(r2), "=r"(r3) : "r"(a));
}
__device__ __forceinline__ void mma_bf16(float* c, const uint32_t* a, uint32_t b0, uint32_t b1) {
    asm volatile(
        "mma.sync.aligned.m16n8k16.row.col.f32.bf16.bf16.f32 "
        "{%0,%1,%2,%3}, {%4,%5,%6,%7}, {%8,%9}, {%0,%1,%2,%3};"
        : "+f"(c[0]), "+f"(c[1]), "+f"(c[2]), "+f"(c[3])
        : "r"(a[0]), "r"(a[1]), "r"(a[2]), "r"(a[3]), "r"(b0), "r"(b1));
}

// =====================================================================
// Tensor-core GEMM via mma.sync: C[M,N] = A[M,K] * W[N,K]^T (+residual)
// fp32 recovered via bf16 hi/lo (Ah*Bh + Ah*Bl + Al*Bh).
// CTA tile 128x128, K-chunk 64, 2-stage cp.async pipeline, 256 threads.
// =====================================================================
#define BM 128
#define BN 128
#define KC 64
#define TILE_B   16384u            // 128 rows * 128 bytes
#define STAGE_B  (4u*TILE_B)       // Ah,Al,Bh,Bl
#define SMEM_GEMM (2u*STAGE_B)     // 131072

// swizzled byte offset within a tile: row in [0,128), seg in [0,8) (16B units)
__device__ __forceinline__ uint32_t swz(int row, int seg) {
    return (uint32_t)(row * 128 + ((seg ^ (row & 7)) << 4));
}

template<bool RES>
__global__ __launch_bounds__(256, 1)
void gemm_mma(const __nv_bfloat16* __restrict__ Ahp, const __nv_bfloat16* __restrict__ Alp,
              const __nv_bfloat16* __restrict__ Bhp, const __nv_bfloat16* __restrict__ Blp,
              const float* __restrict__ resid, float* __restrict__ C,
              int N, int K)
{
    extern __shared__ __align__(1024) char smem[];
    const uint32_t sb = smem_u32(smem);

    const int tid = threadIdx.x;
    const int wid = tid >> 5, lane = tid & 31;
    const int wm = wid & 1, wn = wid >> 1;           // 2 x 4 warp grid
    const int m0 = blockIdx.y * BM, n0 = blockIdx.x * BN;
    const int NC = K / KC;

    // per-thread load mapping: 4 (row,seg) pairs per tile
    int lrow[4], lseg[4];
#pragma unroll
    for (int it = 0; it < 4; it++) {
        int idx = tid + it * 256;
        lrow[it] = idx >> 3;
        lseg[it] = idx & 7;
    }

    // chunk loader
    auto load_chunk = [&](int stage, int k0) {
        uint32_t s = sb + stage * STAGE_B;
#pragma unroll
        for (int it = 0; it < 4; it++) {
            int row = lrow[it], seg = lseg[it];
            uint32_t d = swz(row, seg);
            size_t aoff = (size_t)(m0 + row) * K + k0 + seg * 8;
            cp16(s + d,              Ahp + aoff);
            cp16(s + TILE_B + d,     Alp + aoff);
            int brow = n0 + row; if (brow >= N) brow = N - 1;
            size_t boff = (size_t)brow * K + k0 + seg * 8;
            cp16(s + 2 * TILE_B + d, Bhp + boff);
            cp16(s + 3 * TILE_B + d, Blp + boff);
        }
        cp_commit();
    };

    float acc[4][4][4];
#pragma unroll
    for (int mi = 0; mi < 4; mi++)
#pragma unroll
        for (int ni = 0; ni < 4; ni++)
#pragma unroll
            for (int q = 0; q < 4; q++) acc[mi][ni][q] = 0.f;

    // ldmatrix lane address components
    const int lgrp = lane >> 3, lr = lane & 7;
    // A: row = base + lr + (lgrp&1)*8 ; kseg = k2 + (lgrp>>1)
    const int a_roff = lr + (lgrp & 1) * 8;
    const int a_koff = lgrp >> 1;
    // B: row = base + lr + (lgrp>>1)*8 ; kseg = k2 + (lgrp&1)
    const int b_roff = lr + (lgrp >> 1) * 8;
    const int b_koff = lgrp & 1;

    load_chunk(0, 0);

    for (int c = 0; c < NC; c++) {
        if (c + 1 < NC) { load_chunk((c + 1) & 1, (c + 1) * KC); cp_wait<1>(); }
        else            { cp_wait<0>(); }
        __syncthreads();

        uint32_t s = sb + (c & 1) * STAGE_B;
#pragma unroll
        for (int k16 = 0; k16 < 4; k16++) {
            int k2 = k16 * 2;
            uint32_t ah[4][4], al[4][4], bh[4][2], bl[4][2];
#pragma unroll
            for (int mi = 0; mi < 4; mi++) {
                int row = wm * 64 + mi * 16 + a_roff;
                uint32_t ad = swz(row, k2 + a_koff);
                ldsm_x4(ah[mi][0], ah[mi][1], ah[mi][2], ah[mi][3], s + ad);
                ldsm_x4(al[mi][0], al[mi][1], al[mi][2], al[mi][3], s + TILE_B + ad);
            }
#pragma unroll
            for (int nj = 0; nj < 2; nj++) {
                int row = wn * 32 + nj * 16 + b_roff;
                uint32_t bd = swz(row, k2 + b_koff);
                uint32_t r0, r1, r2, r3;
                ldsm_x4(r0, r1, r2, r3, s + 2 * TILE_B + bd);
                bh[nj * 2][0] = r0; bh[nj * 2][1] = r1; bh[nj * 2 + 1][0] = r2; bh[nj * 2 + 1][1] = r3;
                ldsm_x4(r0, r1, r2, r3, s + 3 * TILE_B + bd);
                bl[nj * 2][0] = r0; bl[nj * 2][1] = r1; bl[nj * 2 + 1][0] = r2; bl[nj * 2 + 1][1] = r3;
            }
#pragma unroll
            for (int mi = 0; mi < 4; mi++)
#pragma unroll
                for (int ni = 0; ni < 4; ni++) {
                    mma_bf16(acc[mi][ni], ah[mi], bh[ni][0], bh[ni][1]);
                    mma_bf16(acc[mi][ni], ah[mi], bl[ni][0], bl[ni][1]);
                    mma_bf16(acc[mi][ni], al[mi], bh[ni][0], bh[ni][1]);
                }
        }
        __syncthreads();
    }

    // ---- epilogue: direct predicated float2 stores ----
    const int quad = lane >> 2, qt = lane & 3;
#pragma unroll
    for (int mi = 0; mi < 4; mi++) {
#pragma unroll
        for (int ni = 0; ni < 4; ni++) {
            int gm = m0 + wm * 64 + mi * 16 + quad;
            int gn = n0 + wn * 32 + ni * 8 + qt * 2;
            if (gn < N) {
                {
                    float2 v = make_float2(acc[mi][ni][0], acc[mi][ni][1]);
                    size_t o = (size_t)gm * N + gn;
                    if (RES) { float2 rv = *(const float2*)(resid + o); v.x += rv.x; v.y += rv.y; }
                    *(float2*)(C + o) = v;
                }
                {
                    float2 v = make_float2(acc[mi][ni][2], acc[mi][ni][3]);
                    size_t o = (size_t)(gm + 8) * N + gn;
                    if (RES) { float2 rv = *(const float2*)(resid + o); v.x += rv.x; v.y += rv.y; }
                    *(float2*)(C + o) = v;
                }
            }
        }
    }
}

// =====================================================================
// fp32 -> bf16 hi/lo split
// =====================================================================
__global__ __launch_bounds__(256)
void cvt_hilo(const float* __restrict__ s, __nv_bfloat16* __restrict__ hi,
              __nv_bfloat16* __restrict__ lo, int n)
{
    int i = blockIdx.x * 256 + threadIdx.x;
    if (i < n) {
        float v = s[i];
        __nv_bfloat16 h = __float2bfloat16(v);
        hi[i] = h;
        lo[i] = __float2bfloat16(v - __bfloat162float(h));
    }
}

// =====================================================================
// Causal depthwise conv (width 4) + bias + SiLU; dt softplus; dA
// =====================================================================
__global__ __launch_bounds__(256)
void conv_act_kernel(const float* __restrict__ conv_w, const float* __restrict__ conv_b,
                     const float* __restrict__ dt_bias, const float* __restrict__ A_log)
{
    const int c = blockIdx.x * 256 + threadIdx.x;
    const int t = blockIdx.y;
    const int b = blockIdx.z;
    const size_t row = (size_t)b * SEQLEN + t;

    if (c < CONVDIM) {
        float acc = conv_b[c];
#pragma unroll
        for (int k = 0; k < DCONV; k++) {
            int tt = t - (DCONV - 1) + k;
            if (tt >= 0)
                acc += g_zx[((size_t)b * SEQLEN + tt) * DINPROJ + DINNER + c] * conv_w[c * DCONV + k];
        }
        g_xbc[row * CONVDIM + c] = acc / (1.f + expf(-acc));
    }
    if (blockIdx.x == 0 && threadIdx.x < NHEADS) {
        int h = threadIdx.x;
        float raw = g_zx[row * DINPROJ + (DINNER + CONVDIM) + h] + dt_bias[h];
        float dtv = (raw > 20.f) ? raw : log1pf(expf(raw));
        g_dt[row * NHEADS + h] = dtv;
        g_dA[row * NHEADS + h] = expf(dtv * (-expf(A_log[h])));
    }
}

// =====================================================================
// Selective scan (unchanged; passed R1)
// =====================================================================
__global__ __launch_bounds__(256)
void scan_kernel()
{
    const int h    = blockIdx.x;
    const int b    = blockIdx.y;
    const int half = blockIdx.z;
    const int tid  = threadIdx.x;
    const int p    = tid >> 2;
    const int ns   = tid & 3;
    const int nbase = half * 64;
    float* __restrict__ yout = half ? g_yp1 : g_yp0;

    __shared__ __align__(16) float sB[8][64];
    __shared__ __align__(16) float sC[8][64];
    __shared__ __align__(16) float sX[8][64];
    __shared__ float sdA[8];
    __shared__ float sdt[8];

    float2 hs[8];
#pragma unroll
    for (int j = 0; j < 8; j++) hs[j] = make_float2(0.f, 0.f);

    for (int t0 = 0; t0 < SEQLEN; t0 += 8) {
        __syncthreads();
#pragma unroll
        for (int it = 0; it < 2; it++) {
            int idx = tid + it * 256;
            int s = idx >> 6, i = idx & 63;
            size_t row = ((size_t)b * SEQLEN + t0 + s) * CONVDIM;
            sB[s][i] = g_xbc[row + DINNER + nbase + i];
            sC[s][i] = g_xbc[row + DINNER + DSTATE + nbase + i];
            sX[s][i] = g_xbc[row + h * HEADDIM + i];
        }
        if (tid < 16) {
            int s = tid & 7;
            size_t r = ((size_t)b * SEQLEN + t0 + s) * NHEADS + h;
            if (tid < 8) sdA[s] = g_dA[r];
            else         sdt[s] = g_dt[r];
        }
        __syncthreads();

#pragma unroll
        for (int s = 0; s < 8; s++) {
            float dAv = sdA[s];
            float2 dA2 = make_float2(dAv, dAv);
            float coef = sdt[s] * sX[s][p];
            float2 c2  = make_float2(coef, coef);
            float2 acc = make_float2(0.f, 0.f);
#pragma unroll
            for (int j = 0; j < 8; j++) {
                int no = ns * 2 + j * 8;
                float2 Bj = *reinterpret_cast<const float2*>(&sB[s][no]);
                float2 Cj = *reinterpret_cast<const float2*>(&sC[s][no]);
                hs[j] = ffma2(hs[j], dA2, fmul2(c2, Bj));
                acc   = ffma2(hs[j], Cj, acc);
            }
            float y = acc.x + acc.y;
            y += __shfl_down_sync(0xffffffffu, y, 2, 4);
            y += __shfl_down_sync(0xffffffffu, y, 1, 4);
            if (ns == 0)
                yout[((size_t)b * SEQLEN + t0 + s) * DINNER + h * HEADDIM + p] = y;
        }
    }
}

// =====================================================================
// skip + gate + RMSNorm -> bf16 hi/lo for GEMM2
// =====================================================================
__global__ __launch_bounds__(256)
void gate_norm_kernel(const float* __restrict__ Dw, const float* __restrict__ norm_w)
{
    const int t = blockIdx.x;
    const int b = blockIdx.y;
    const size_t row = (size_t)b * SEQLEN + t;
    const float* __restrict__ zrow = &g_zx [row * DINPROJ];
    const float* __restrict__ xrow = &g_xbc[row * CONVDIM];
    const float* __restrict__ y0   = &g_yp0[row * DINNER];
    const float* __restrict__ y1   = &g_yp1[row * DINNER];

    float vals[8];
    float ss = 0.f;
#pragma unroll
    for (int r = 0; r < 8; r++) {
        int c = r * 256 + threadIdx.x;
        int hh = c >> 6;
        float v = y0[c] + y1[c] + Dw[hh] * xrow[c];
        float z = zrow[c];
        v *= z / (1.f + expf(-z));
        vals[r] = v;
        ss += v * v;
    }
    __shared__ float red[256];
    red[threadIdx.x] = ss;
    __syncthreads();
    for (int off = 128; off > 0; off >>= 1) {
        if (threadIdx.x < off) red[threadIdx.x] += red[threadIdx.x + off];
        __syncthreads();
    }
    float scale = rsqrtf(red[0] / (float)DINNER + EPS);
#pragma unroll
    for (int r = 0; r < 8; r++) {
        int c = r * 256 + threadIdx.x;
        float v = vals[r] * scale * norm_w[c];
        __nv_bfloat16 h = __float2bfloat16(v);
        g_ynh[row * DINNER + c] = h;
        g_ynl[row * DINNER + c] = __float2bfloat16(v - __bfloat162float(h));
    }
}

// =====================================================================
extern "C" void kernel_launch(void* const* d_in, const int* in_sizes, int n_in,
                              void* d_out, int out_size)
{
    const float* x          = (const float*)d_in[0];
    const float* in_proj_w  = (const float*)d_in[1];
    const float* conv_w     = (const float*)d_in[2];
    const float* conv_b     = (const float*)d_in[3];
    const float* dt_bias    = (const float*)d_in[4];
    const float* A_log      = (const float*)d_in[5];
    const float* Dw         = (const float*)d_in[6];
    const float* norm_w     = (const float*)d_in[7];
    const float* out_proj_w = (const float*)d_in[8];
    float* out = (float*)d_out;

    float *p_zx = nullptr;
    void *p_xh, *p_xl, *p_w1h, *p_w1l, *p_w2h, *p_w2l, *p_ynh, *p_ynl;
    cudaGetSymbolAddress((void**)&p_zx, g_zx);
    cudaGetSymbolAddress(&p_xh,  g_xh);  cudaGetSymbolAddress(&p_xl,  g_xl);
    cudaGetSymbolAddress(&p_w1h, g_w1h); cudaGetSymbolAddress(&p_w1l, g_w1l);
    cudaGetSymbolAddress(&p_w2h, g_w2h); cudaGetSymbolAddress(&p_w2l, g_w2l);
    cudaGetSymbolAddress(&p_ynh, g_ynh); cudaGetSymbolAddress(&p_ynl, g_ynl);

    cudaFuncSetAttribute(gemm_mma<false>, cudaFuncAttributeMaxDynamicSharedMemorySize, SMEM_GEMM);
    cudaFuncSetAttribute(gemm_mma<true>,  cudaFuncAttributeMaxDynamicSharedMemorySize, SMEM_GEMM);

    // 0) fp32 -> bf16 hi/lo conversions
    cvt_hilo<<<(ROWS*DMODEL + 255)/256, 256>>>(x, (__nv_bfloat16*)p_xh, (__nv_bfloat16*)p_xl, ROWS*DMODEL);
    cvt_hilo<<<(DINPROJ*DMODEL + 255)/256, 256>>>(in_proj_w, (__nv_bfloat16*)p_w1h, (__nv_bfloat16*)p_w1l, DINPROJ*DMODEL);
    cvt_hilo<<<(DMODEL*DINNER + 255)/256, 256>>>(out_proj_w, (__nv_bfloat16*)p_w2h, (__nv_bfloat16*)p_w2l, DMODEL*DINNER);

    // 1) zxbcdt = x @ in_proj_w^T   [2048 x 4384]
    gemm_mma<false><<<dim3((DINPROJ + BN - 1)/BN, ROWS/BM), 256, SMEM_GEMM>>>(
        (const __nv_bfloat16*)p_xh, (const __nv_bfloat16*)p_xl,
        (const __nv_bfloat16*)p_w1h, (const __nv_bfloat16*)p_w1l,
        nullptr, p_zx, DINPROJ, DMODEL);

    // 2) conv + SiLU; dt/dA
    conv_act_kernel<<<dim3(CONVDIM/256, SEQLEN, BATCH), 256>>>(conv_w, conv_b, dt_bias, A_log);

    // 3) selective scan
    scan_kernel<<<dim3(NHEADS, BATCH, 2), 256>>>();

    // 4) skip + gate + RMSNorm (emits bf16 hi/lo)
    gate_norm_kernel<<<dim3(SEQLEN, BATCH), 256>>>(Dw, norm_w);

    // 5) out = x + yn @ out_proj_w^T   [2048 x 1024]
    gemm_mma<true><<<dim3(DMODEL/BN, ROWS/BM), 256, SMEM_GEMM>>>(
        (const __nv_bfloat16*)p_ynh, (const __nv_bfloat16*)p_ynl,
        (const __nv_bfloat16*)p_w2h, (const __nv_bfloat16*)p_w2l,
        x, out, DMODEL, DINNER);
}

// round 4
// speedup vs baseline: 2.6126x; 1.1334x over previous
#include <cuda_runtime.h>
#include <cuda_bf16.h>
#include <math.h>
#include <stdint.h>

// ---------------- problem constants ----------------
#define BATCH    2
#define SEQLEN   1024
#define DMODEL   1024
#define DINNER   2048
#define NHEADS   32
#define HEADDIM  64
#define DSTATE   128
#define DCONV    4
#define CONVDIM  2304          // DINNER + 2*DSTATE
#define DINPROJ  4384          // 2*DINNER + 2*DSTATE + NHEADS
#define ROWS     (BATCH*SEQLEN)   // 2048
#define EPS      1e-5f

// ---------------- scratch (static device allocations only) ----------------
__device__ __align__(1024) float g_zx [ROWS*DINPROJ];
__device__ __align__(1024) float g_xbc[ROWS*CONVDIM];
__device__ __align__(1024) float g_dt [ROWS*NHEADS];
__device__ __align__(1024) float g_dA [ROWS*NHEADS];
__device__ __align__(1024) float g_yp0[ROWS*DINNER];
__device__ __align__(1024) float g_yp1[ROWS*DINNER];
__device__ __align__(1024) float g_yp2[ROWS*DINNER];
__device__ __align__(1024) float g_yp3[ROWS*DINNER];
__device__ __align__(1024) __nv_bfloat16 g_xh [ROWS*DMODEL];
__device__ __align__(1024) __nv_bfloat16 g_xl [ROWS*DMODEL];
__device__ __align__(1024) __nv_bfloat16 g_w1h[DINPROJ*DMODEL];
__device__ __align__(1024) __nv_bfloat16 g_w1l[DINPROJ*DMODEL];
__device__ __align__(1024) __nv_bfloat16 g_w2h[DMODEL*DINNER];
__device__ __align__(1024) __nv_bfloat16 g_w2l[DMODEL*DINNER];
__device__ __align__(1024) __nv_bfloat16 g_ynh[ROWS*DINNER];
__device__ __align__(1024) __nv_bfloat16 g_ynl[ROWS*DINNER];

// ---------------- packed f32x2 helpers ----------------
__device__ __forceinline__ float2 ffma2(float2 a, float2 b, float2 c) {
    float2 d;
    asm("fma.rn.f32x2 %0, %1, %2, %3;"
        : "=l"(reinterpret_cast<unsigned long long &>(d))
        : "l"(reinterpret_cast<const unsigned long long &>(a)),
          "l"(reinterpret_cast<const unsigned long long &>(b)),
          "l"(reinterpret_cast<const unsigned long long &>(c)));
    return d;
}
__device__ __forceinline__ float2 fmul2(float2 a, float2 b) {
    float2 d;
    asm("mul.rn.f32x2 %0, %1, %2;"
        : "=l"(reinterpret_cast<unsigned long long &>(d))
        : "l"(reinterpret_cast<const unsigned long long &>(a)),
          "l"(reinterpret_cast<const unsigned long long &>(b)));
    return d;
}

// ---------------- sm_80-era primitives ----------
__device__ __forceinline__ uint32_t smem_u32(const void* p) {
    uint32_t a;
    asm("{ .reg .u64 t; cvta.to.shared.u64 t, %1; cvt.u32.u64 %0, t; }" : "=r"(a) : "l"(p));
    return a;
}
__device__ __forceinline__ void cp16(uint32_t dst, const void* src) {
    asm volatile("cp.async.cg.shared.global [%0], [%1], 16;" :: "r"(dst), "l"(src));
}
__device__ __forceinline__ void cp_commit() { asm volatile("cp.async.commit_group;" ::: "memory"); }
template<int W> __device__ __forceinline__ void cp_wait() {
    asm volatile("cp.async.wait_group %0;" :: "n"(W) : "memory");
}
__device__ __forceinline__ void ldsm_x4(uint32_t& r0, uint32_t& r1, uint32_t& r2, uint32_t& r3, uint32_t a) {
    asm volatile("ldmatrix.sync.aligned.m8n8.x4.shared.b16 {%0,%1,%2,%3}, [%4];"
                 : "=r"(r0), "=r"(r1), "=r"(r2), "=r"(r3) : "r"(a));
}
__device__ __forceinline__ void mma_bf16(float* c, const uint32_t* a, uint32_t b0, uint32_t b1) {
    asm volatile(
        "mma.sync.aligned.m16n8k16.row.col.f32.bf16.bf16.f32 "
        "{%0,%1,%2,%3}, {%4,%5,%6,%7}, {%8,%9}, {%0,%1,%2,%3};"
        : "+f"(c[0]), "+f"(c[1]), "+f"(c[2]), "+f"(c[3])
        : "r"(a[0]), "r"(a[1]), "r"(a[2]), "r"(a[3]), "r"(b0), "r"(b1));
}

// =====================================================================
// Tensor-core GEMM via mma.sync: C[M,N] = A[M,K] * W[N,K]^T (+residual)
// fp32 via bf16 hi/lo (Ah*Bh + Ah*Bl + Al*Bh).
// CTA tile 128x128, K-chunk 64, 3-stage cp.async pipeline, 256 threads.
// =====================================================================
#define BM 128
#define BN 128
#define KC 64
#define TILE_B   16384u            // 128 rows * 128 bytes
#define STAGE_B  (4u*TILE_B)       // Ah,Al,Bh,Bl
#define NSTAGE   3
#define SMEM_GEMM (NSTAGE*STAGE_B) // 196608

__device__ __forceinline__ uint32_t swz(int row, int seg) {
    return (uint32_t)(row * 128 + ((seg ^ (row & 7)) << 4));
}

template<bool RES>
__global__ __launch_bounds__(256, 1)
void gemm_mma(const __nv_bfloat16* __restrict__ Ahp, const __nv_bfloat16* __restrict__ Alp,
              const __nv_bfloat16* __restrict__ Bhp, const __nv_bfloat16* __restrict__ Blp,
              const float* __restrict__ resid, float* __restrict__ C,
              int N, int K)
{
    extern __shared__ __align__(1024) char smem[];
    const uint32_t sb = smem_u32(smem);

    const int tid = threadIdx.x;
    const int wid = tid >> 5, lane = tid & 31;
    const int wm = wid & 1, wn = wid >> 1;           // 2 x 4 warp grid
    const int m0 = blockIdx.y * BM, n0 = blockIdx.x * BN;
    const int NC = K / KC;

    int lrow[4], lseg[4];
#pragma unroll
    for (int it = 0; it < 4; it++) {
        int idx = tid + it * 256;
        lrow[it] = idx >> 3;
        lseg[it] = idx & 7;
    }

    auto load_chunk = [&](int stage, int k0) {
        uint32_t s = sb + stage * STAGE_B;
#pragma unroll
        for (int it = 0; it < 4; it++) {
            int row = lrow[it], seg = lseg[it];
            uint32_t d = swz(row, seg);
            size_t aoff = (size_t)(m0 + row) * K + k0 + seg * 8;
            cp16(s + d,              Ahp + aoff);
            cp16(s + TILE_B + d,     Alp + aoff);
            int brow = n0 + row; if (brow >= N) brow = N - 1;
            size_t boff = (size_t)brow * K + k0 + seg * 8;
            cp16(s + 2 * TILE_B + d, Bhp + boff);
            cp16(s + 3 * TILE_B + d, Blp + boff);
        }
        cp_commit();
    };

    float acc[4][4][4];
#pragma unroll
    for (int mi = 0; mi < 4; mi++)
#pragma unroll
        for (int ni = 0; ni < 4; ni++)
#pragma unroll
            for (int q = 0; q < 4; q++) acc[mi][ni][q] = 0.f;

    const int lgrp = lane >> 3, lr = lane & 7;
    const int a_roff = lr + (lgrp & 1) * 8;
    const int a_koff = lgrp >> 1;
    const int b_roff = lr + (lgrp >> 1) * 8;
    const int b_koff = lgrp & 1;

    load_chunk(0, 0);
    load_chunk(1, KC);

    for (int c = 0; c < NC; c++) {
        if (c + 2 < NC) load_chunk((c + 2) % NSTAGE, (c + 2) * KC);
        else            cp_commit();                 // keep group count constant
        cp_wait<2>();                                // chunk c resident
        __syncthreads();

        uint32_t s = sb + (c % NSTAGE) * STAGE_B;
#pragma unroll
        for (int k16 = 0; k16 < 4; k16++) {
            int k2 = k16 * 2;
            uint32_t ah[4][4], al[4][4], bh[4][2], bl[4][2];
#pragma unroll
            for (int mi = 0; mi < 4; mi++) {
                int row = wm * 64 + mi * 16 + a_roff;
                uint32_t ad = swz(row, k2 + a_koff);
                ldsm_x4(ah[mi][0], ah[mi][1], ah[mi][2], ah[mi][3], s + ad);
                ldsm_x4(al[mi][0], al[mi][1], al[mi][2], al[mi][3], s + TILE_B + ad);
            }
#pragma unroll
            for (int nj = 0; nj < 2; nj++) {
                int row = wn * 32 + nj * 16 + b_roff;
                uint32_t bd = swz(row, k2 + b_koff);
                uint32_t r0, r1, r2, r3;
                ldsm_x4(r0, r1, r2, r3, s + 2 * TILE_B + bd);
                bh[nj * 2][0] = r0; bh[nj * 2][1] = r1; bh[nj * 2 + 1][0] = r2; bh[nj * 2 + 1][1] = r3;
                ldsm_x4(r0, r1, r2, r3, s + 3 * TILE_B + bd);
                bl[nj * 2][0] = r0; bl[nj * 2][1] = r1; bl[nj * 2 + 1][0] = r2; bl[nj * 2 + 1][1] = r3;
            }
#pragma unroll
            for (int mi = 0; mi < 4; mi++)
#pragma unroll
                for (int ni = 0; ni < 4; ni++) {
                    mma_bf16(acc[mi][ni], ah[mi], bh[ni][0], bh[ni][1]);
                    mma_bf16(acc[mi][ni], ah[mi], bl[ni][0], bl[ni][1]);
                    mma_bf16(acc[mi][ni], al[mi], bh[ni][0], bh[ni][1]);
                }
        }
        __syncthreads();
    }

    // ---- epilogue ----
    const int quad = lane >> 2, qt = lane & 3;
#pragma unroll
    for (int mi = 0; mi < 4; mi++) {
#pragma unroll
        for (int ni = 0; ni < 4; ni++) {
            int gm = m0 + wm * 64 + mi * 16 + quad;
            int gn = n0 + wn * 32 + ni * 8 + qt * 2;
            if (gn < N) {
                {
                    float2 v = make_float2(acc[mi][ni][0], acc[mi][ni][1]);
                    size_t o = (size_t)gm * N + gn;
                    if (RES) { float2 rv = *(const float2*)(resid + o); v.x += rv.x; v.y += rv.y; }
                    *(float2*)(C + o) = v;
                }
                {
                    float2 v = make_float2(acc[mi][ni][2], acc[mi][ni][3]);
                    size_t o = (size_t)(gm + 8) * N + gn;
                    if (RES) { float2 rv = *(const float2*)(resid + o); v.x += rv.x; v.y += rv.y; }
                    *(float2*)(C + o) = v;
                }
            }
        }
    }
}

// =====================================================================
// fp32 -> bf16 hi/lo split, vectorized x4
// =====================================================================
__global__ __launch_bounds__(256)
void cvt_hilo4(const float4* __restrict__ s, __nv_bfloat162* __restrict__ hi,
               __nv_bfloat162* __restrict__ lo, int n4)
{
    int i = blockIdx.x * 256 + threadIdx.x;
    if (i < n4) {
        float4 v = s[i];
        __nv_bfloat16 hx = __float2bfloat16(v.x);
        __nv_bfloat16 hy = __float2bfloat16(v.y);
        __nv_bfloat16 hz = __float2bfloat16(v.z);
        __nv_bfloat16 hw = __float2bfloat16(v.w);
        hi[i * 2]     = __halves2bfloat162(hx, hy);
        hi[i * 2 + 1] = __halves2bfloat162(hz, hw);
        lo[i * 2]     = __halves2bfloat162(__float2bfloat16(v.x - __bfloat162float(hx)),
                                           __float2bfloat16(v.y - __bfloat162float(hy)));
        lo[i * 2 + 1] = __halves2bfloat162(__float2bfloat16(v.z - __bfloat162float(hz)),
                                           __float2bfloat16(v.w - __bfloat162float(hw)));
    }
}

// =====================================================================
// Causal depthwise conv (width 4) + bias + SiLU; dt softplus; dA
// 4 timesteps per thread (sliding window)
// =====================================================================
__global__ __launch_bounds__(256)
void conv_act_kernel(const float* __restrict__ conv_w, const float* __restrict__ conv_b,
                     const float* __restrict__ dt_bias, const float* __restrict__ A_log)
{
    const int c  = blockIdx.x * 256 + threadIdx.x;   // < CONVDIM (grid.x = 9)
    const int tb = blockIdx.y * 4;
    const int b  = blockIdx.z;

    float w0 = conv_w[c * 4 + 0], w1 = conv_w[c * 4 + 1];
    float w2 = conv_w[c * 4 + 2], w3 = conv_w[c * 4 + 3];
    float bias = conv_b[c];

    float v[7];
#pragma unroll
    for (int k = 0; k < 7; k++) {
        int tt = tb - 3 + k;
        v[k] = (tt >= 0) ? g_zx[((size_t)b * SEQLEN + tt) * DINPROJ + DINNER + c] : 0.f;
    }
#pragma unroll
    for (int i = 0; i < 4; i++) {
        float a = bias + v[i] * w0 + v[i + 1] * w1 + v[i + 2] * w2 + v[i + 3] * w3;
        g_xbc[((size_t)b * SEQLEN + tb + i) * CONVDIM + c] = a / (1.f + expf(-a));
    }
    if (blockIdx.x == 0 && threadIdx.x < NHEADS) {
        int hh = threadIdx.x;
        float negA = -expf(A_log[hh]);
        float bth  = dt_bias[hh];
#pragma unroll
        for (int i = 0; i < 4; i++) {
            size_t row = (size_t)b * SEQLEN + tb + i;
            float raw = g_zx[row * DINPROJ + (DINNER + CONVDIM) + hh] + bth;
            float dtv = (raw > 20.f) ? raw : log1pf(expf(raw));
            g_dt[row * NHEADS + hh] = dtv;
            g_dA[row * NHEADS + hh] = expf(dtv * negA);
        }
    }
}

// =====================================================================
// Selective scan: grid (NHEADS, BATCH, 4 n-quarters) = 256 blocks.
// 256 threads: p = tid>>2 in [0,64), ns = tid&3; thread owns 8 states
// (2 float4 groups at n = ns*4 + j*16). LDS.128 B/C reads.
// =====================================================================
__global__ __launch_bounds__(256)
void scan_kernel()
{
    const int h = blockIdx.x, b = blockIdx.y, q = blockIdx.z;
    const int tid = threadIdx.x;
    const int p = tid >> 2, ns = tid & 3;
    const int nbase = q * 32;
    float* __restrict__ yout = (q == 0) ? g_yp0 : (q == 1) ? g_yp1 : (q == 2) ? g_yp2 : g_yp3;

    __shared__ __align__(16) float sB[8][32];
    __shared__ __align__(16) float sC[8][32];
    __shared__ __align__(16) float sX[8][64];
    __shared__ float sdA[8], sdt[8];

    float2 hs[4];
#pragma unroll
    for (int j = 0; j < 4; j++) hs[j] = make_float2(0.f, 0.f);

    for (int t0 = 0; t0 < SEQLEN; t0 += 8) {
        __syncthreads();
        {
            int idx = tid;
            if (idx < 64) {                    // B quarter: 8 s x 8 float4
                int s = idx >> 3, f = idx & 7;
                size_t row = ((size_t)b * SEQLEN + t0 + s) * CONVDIM;
                *(float4*)&sB[s][f * 4] = *(const float4*)&g_xbc[row + DINNER + nbase + f * 4];
            } else if (idx < 128) {            // C quarter
                int r = idx - 64; int s = r >> 3, f = r & 7;
                size_t row = ((size_t)b * SEQLEN + t0 + s) * CONVDIM;
                *(float4*)&sC[s][f * 4] = *(const float4*)&g_xbc[row + DINNER + DSTATE + nbase + f * 4];
            } else {                           // X head slice: 8 s x 16 float4
                int r = idx - 128; int s = r >> 4, f = r & 15;
                size_t row = ((size_t)b * SEQLEN + t0 + s) * CONVDIM;
                *(float4*)&sX[s][f * 4] = *(const float4*)&g_xbc[row + h * HEADDIM + f * 4];
            }
            if (tid < 16) {
                int s = tid & 7;
                size_t r = ((size_t)b * SEQLEN + t0 + s) * NHEADS + h;
                if (tid < 8) sdA[s] = g_dA[r];
                else         sdt[s] = g_dt[r];
            }
        }
        __syncthreads();

#pragma unroll
        for (int s = 0; s < 8; s++) {
            float dAv = sdA[s];
            float2 dA2 = make_float2(dAv, dAv);
            float coef = sdt[s] * sX[s][p];
            float2 c2  = make_float2(coef, coef);
            float4 B0 = *(const float4*)&sB[s][ns * 4];
            float4 B1 = *(const float4*)&sB[s][ns * 4 + 16];
            float4 C0 = *(const float4*)&sC[s][ns * 4];
            float4 C1 = *(const float4*)&sC[s][ns * 4 + 16];
            float2 acc = make_float2(0.f, 0.f);
            hs[0] = ffma2(hs[0], dA2, fmul2(c2, make_float2(B0.x, B0.y)));
            acc   = ffma2(hs[0], make_float2(C0.x, C0.y), acc);
            hs[1] = ffma2(hs[1], dA2, fmul2(c2, make_float2(B0.z, B0.w)));
            acc   = ffma2(hs[1], make_float2(C0.z, C0.w), acc);
            hs[2] = ffma2(hs[2], dA2, fmul2(c2, make_float2(B1.x, B1.y)));
            acc   = ffma2(hs[2], make_float2(C1.x, C1.y), acc);
            hs[3] = ffma2(hs[3], dA2, fmul2(c2, make_float2(B1.z, B1.w)));
            acc   = ffma2(hs[3], make_float2(C1.z, C1.w), acc);
            float y = acc.x + acc.y;
            y += __shfl_down_sync(0xffffffffu, y, 2, 4);
            y += __shfl_down_sync(0xffffffffu, y, 1, 4);
            if (ns == 0)
                yout[((size_t)b * SEQLEN + t0 + s) * DINNER + h * HEADDIM + p] = y;
        }
    }
}

// =====================================================================
// skip + gate + RMSNorm -> bf16 hi/lo for GEMM2 (sums 4 scan partials)
// =====================================================================
__global__ __launch_bounds__(256)
void gate_norm_kernel(const float* __restrict__ Dw, const float* __restrict__ norm_w)
{
    const int t = blockIdx.x;
    const int b = blockIdx.y;
    const size_t row = (size_t)b * SEQLEN + t;
    const float* __restrict__ zrow = &g_zx [row * DINPROJ];
    const float* __restrict__ xrow = &g_xbc[row * CONVDIM];
    const float* __restrict__ y0 = &g_yp0[row * DINNER];
    const float* __restrict__ y1 = &g_yp1[row * DINNER];
    const float* __restrict__ y2 = &g_yp2[row * DINNER];
    const float* __restrict__ y3 = &g_yp3[row * DINNER];

    float vals[8];
    float ss = 0.f;
#pragma unroll
    for (int r = 0; r < 8; r++) {
        int c = r * 256 + threadIdx.x;
        int hh = c >> 6;
        float v = (y0[c] + y1[c]) + (y2[c] + y3[c]) + Dw[hh] * xrow[c];
        float z = zrow[c];
        v *= z / (1.f + expf(-z));
        vals[r] = v;
        ss += v * v;
    }
    __shared__ float red[256];
    red[threadIdx.x] = ss;
    __syncthreads();
    for (int off = 128; off > 0; off >>= 1) {
        if (threadIdx.x < off) red[threadIdx.x] += red[threadIdx.x + off];
        __syncthreads();
    }
    float scale = rsqrtf(red[0] / (float)DINNER + EPS);
#pragma unroll
    for (int r = 0; r < 8; r++) {
        int c = r * 256 + threadIdx.x;
        float v = vals[r] * scale * norm_w[c];
        __nv_bfloat16 hv = __float2bfloat16(v);
        g_ynh[row * DINNER + c] = hv;
        g_ynl[row * DINNER + c] = __float2bfloat16(v - __bfloat162float(hv));
    }
}

// =====================================================================
extern "C" void kernel_launch(void* const* d_in, const int* in_sizes, int n_in,
                              void* d_out, int out_size)
{
    const float* x          = (const float*)d_in[0];
    const float* in_proj_w  = (const float*)d_in[1];
    const float* conv_w     = (const float*)d_in[2];
    const float* conv_b     = (const float*)d_in[3];
    const float* dt_bias    = (const float*)d_in[4];
    const float* A_log      = (const float*)d_in[5];
    const float* Dw         = (const float*)d_in[6];
    const float* norm_w     = (const float*)d_in[7];
    const float* out_proj_w = (const float*)d_in[8];
    float* out = (float*)d_out;

    float *p_zx = nullptr;
    void *p_xh, *p_xl, *p_w1h, *p_w1l, *p_w2h, *p_w2l, *p_ynh, *p_ynl;
    cudaGetSymbolAddress((void**)&p_zx, g_zx);
    cudaGetSymbolAddress(&p_xh,  g_xh);  cudaGetSymbolAddress(&p_xl,  g_xl);
    cudaGetSymbolAddress(&p_w1h, g_w1h); cudaGetSymbolAddress(&p_w1l, g_w1l);
    cudaGetSymbolAddress(&p_w2h, g_w2h); cudaGetSymbolAddress(&p_w2l, g_w2l);
    cudaGetSymbolAddress(&p_ynh, g_ynh); cudaGetSymbolAddress(&p_ynl, g_ynl);

    cudaFuncSetAttribute(gemm_mma<false>, cudaFuncAttributeMaxDynamicSharedMemorySize, SMEM_GEMM);
    cudaFuncSetAttribute(gemm_mma<true>,  cudaFuncAttributeMaxDynamicSharedMemorySize, SMEM_GEMM);

    // 0) fp32 -> bf16 hi/lo conversions (vectorized)
    cvt_hilo4<<<(ROWS*DMODEL/4 + 255)/256, 256>>>(
        (const float4*)x, (__nv_bfloat162*)p_xh, (__nv_bfloat162*)p_xl, ROWS*DMODEL/4);
    cvt_hilo4<<<(DINPROJ*DMODEL/4 + 255)/256, 256>>>(
        (const float4*)in_proj_w, (__nv_bfloat162*)p_w1h, (__nv_bfloat162*)p_w1l, DINPROJ*DMODEL/4);
    cvt_hilo4<<<(DMODEL*DINNER/4 + 255)/256, 256>>>(
        (const float4*)out_proj_w, (__nv_bfloat162*)p_w2h, (__nv_bfloat162*)p_w2l, DMODEL*DINNER/4);

    // 1) zxbcdt = x @ in_proj_w^T   [2048 x 4384]
    gemm_mma<false><<<dim3((DINPROJ + BN - 1)/BN, ROWS/BM), 256, SMEM_GEMM>>>(
        (const __nv_bfloat16*)p_xh, (const __nv_bfloat16*)p_xl,
        (const __nv_bfloat16*)p_w1h, (const __nv_bfloat16*)p_w1l,
        nullptr, p_zx, DINPROJ, DMODEL);

    // 2) conv + SiLU; dt/dA
    conv_act_kernel<<<dim3(CONVDIM/256, SEQLEN/4, BATCH), 256>>>(conv_w, conv_b, dt_bias, A_log);

    // 3) selective scan (4 state-quarters)
    scan_kernel<<<dim3(NHEADS, BATCH, 4), 256>>>();

    // 4) skip + gate + RMSNorm (emits bf16 hi/lo)
    gate_norm_kernel<<<dim3(SEQLEN, BATCH), 256>>>(Dw, norm_w);

    // 5) out = x + yn @ out_proj_w^T   [2048 x 1024]
    gemm_mma<true><<<dim3(DMODEL/BN, ROWS/BM), 256, SMEM_GEMM>>>(
        (const __nv_bfloat16*)p_ynh, (const __nv_bfloat16*)p_ynl,
        (const __nv_bfloat16*)p_w2h, (const __nv_bfloat16*)p_w2l,
        x, out, DMODEL, DINNER);
}

// round 5
// speedup vs baseline: 2.6162x; 1.0014x over previous
#include <cuda_runtime.h>
#include <cuda_bf16.h>
#include <math.h>
#include <stdint.h>

// ---------------- problem constants ----------------
#define BATCH    2
#define SEQLEN   1024
#define DMODEL   1024
#define DINNER   2048
#define NHEADS   32
#define HEADDIM  64
#define DSTATE   128
#define DCONV    4
#define CONVDIM  2304          // DINNER + 2*DSTATE
#define DINPROJ  4384          // 2*DINNER + 2*DSTATE + NHEADS
#define ROWS     (BATCH*SEQLEN)   // 2048
#define EPS      1e-5f

// ---------------- scratch (static device allocations only) ----------------
__device__ __align__(1024) float g_zx [ROWS*DINPROJ];
__device__ __align__(1024) float g_xbc[ROWS*CONVDIM];
__device__ __align__(1024) float g_dt [ROWS*NHEADS];
__device__ __align__(1024) float g_dA [ROWS*NHEADS];
__device__ __align__(1024) float g_yp0[ROWS*DINNER];
__device__ __align__(1024) float g_yp1[ROWS*DINNER];
__device__ __align__(1024) float g_yp2[ROWS*DINNER];
__device__ __align__(1024) float g_yp3[ROWS*DINNER];
__device__ __align__(1024) __nv_bfloat16 g_xh [ROWS*DMODEL];
__device__ __align__(1024) __nv_bfloat16 g_xl [ROWS*DMODEL];
__device__ __align__(1024) __nv_bfloat16 g_w1h[DINPROJ*DMODEL];
__device__ __align__(1024) __nv_bfloat16 g_w1l[DINPROJ*DMODEL];
__device__ __align__(1024) __nv_bfloat16 g_w2h[DMODEL*DINNER];
__device__ __align__(1024) __nv_bfloat16 g_w2l[DMODEL*DINNER];
__device__ __align__(1024) __nv_bfloat16 g_ynh[ROWS*DINNER];
__device__ __align__(1024) __nv_bfloat16 g_ynl[ROWS*DINNER];

// ---------------- packed f32x2 helpers ----------------
__device__ __forceinline__ float2 ffma2(float2 a, float2 b, float2 c) {
    float2 d;
    asm("fma.rn.f32x2 %0, %1, %2, %3;"
        : "=l"(reinterpret_cast<unsigned long long &>(d))
        : "l"(reinterpret_cast<const unsigned long long &>(a)),
          "l"(reinterpret_cast<const unsigned long long &>(b)),
          "l"(reinterpret_cast<const unsigned long long &>(c)));
    return d;
}
__device__ __forceinline__ float2 fmul2(float2 a, float2 b) {
    float2 d;
    asm("mul.rn.f32x2 %0, %1, %2;"
        : "=l"(reinterpret_cast<unsigned long long &>(d))
        : "l"(reinterpret_cast<const unsigned long long &>(a)),
          "l"(reinterpret_cast<const unsigned long long &>(b)));
    return d;
}

// ---------------- sm_80-era primitives ----------
__device__ __forceinline__ uint32_t smem_u32(const void* p) {
    uint32_t a;
    asm("{ .reg .u64 t; cvta.to.shared.u64 t, %1; cvt.u32.u64 %0, t; }" : "=r"(a) : "l"(p));
    return a;
}
__device__ __forceinline__ void cp16(uint32_t dst, const void* src) {
    asm volatile("cp.async.cg.shared.global [%0], [%1], 16;" :: "r"(dst), "l"(src));
}
__device__ __forceinline__ void cp_commit() { asm volatile("cp.async.commit_group;" ::: "memory"); }
template<int W> __device__ __forceinline__ void cp_wait() {
    asm volatile("cp.async.wait_group %0;" :: "n"(W) : "memory");
}
__device__ __forceinline__ void ldsm_x4(uint32_t& r0, uint32_t& r1, uint32_t& r2, uint32_t& r3, uint32_t a) {
    asm volatile("ldmatrix.sync.aligned.m8n8.x4.shared.b16 {%0,%1,%2,%3}, [%4];"
                 : "=r"(r0), "=r"(r1), "=r"(r2), "=r"(r3) : "r"(a));
}
__device__ __forceinline__ void mma_bf16(float* c, const uint32_t* a, uint32_t b0, uint32_t b1) {
    asm volatile(
        "mma.sync.aligned.m16n8k16.row.col.f32.bf16.bf16.f32 "
        "{%0,%1,%2,%3}, {%4,%5,%6,%7}, {%8,%9}, {%0,%1,%2,%3};"
        : "+f"(c[0]), "+f"(c[1]), "+f"(c[2]), "+f"(c[3])
        : "r"(a[0]), "r"(a[1]), "r"(a[2]), "r"(a[3]), "r"(b0), "r"(b1));
}

// =====================================================================
// Tensor-core GEMM via mma.sync: C[M,N] = A[M,K] * W[N,K]^T (+residual)
// fp32 via bf16 hi/lo (Ah*Bh + Ah*Bl + Al*Bh).
// CTA tile 128x128, K-chunk 64, 3-stage cp.async pipeline, 256 threads.
// Inner k16 loop uses explicit double-buffered ldmatrix fragments so the
// tensor pipe never waits on shared-memory latency.
// =====================================================================
#define BM 128
#define BN 128
#define KC 64
#define TILE_B   16384u            // 128 rows * 128 bytes
#define STAGE_B  (4u*TILE_B)       // Ah,Al,Bh,Bl
#define NSTAGE   3
#define SMEM_GEMM (NSTAGE*STAGE_B) // 196608

__device__ __forceinline__ uint32_t swz(int row, int seg) {
    return (uint32_t)(row * 128 + ((seg ^ (row & 7)) << 4));
}

template<bool RES>
__global__ __launch_bounds__(256, 1)
void gemm_mma(const __nv_bfloat16* __restrict__ Ahp, const __nv_bfloat16* __restrict__ Alp,
              const __nv_bfloat16* __restrict__ Bhp, const __nv_bfloat16* __restrict__ Blp,
              const float* __restrict__ resid, float* __restrict__ C,
              int N, int K)
{
    extern __shared__ __align__(1024) char smem[];
    const uint32_t sb = smem_u32(smem);

    const int tid = threadIdx.x;
    const int wid = tid >> 5, lane = tid & 31;
    const int wm = wid & 1, wn = wid >> 1;           // 2 x 4 warp grid
    const int m0 = blockIdx.y * BM, n0 = blockIdx.x * BN;
    const int NC = K / KC;

    int lrow[4], lseg[4];
#pragma unroll
    for (int it = 0; it < 4; it++) {
        int idx = tid + it * 256;
        lrow[it] = idx >> 3;
        lseg[it] = idx & 7;
    }

    auto load_chunk = [&](int stage, int k0) {
        uint32_t s = sb + stage * STAGE_B;
#pragma unroll
        for (int it = 0; it < 4; it++) {
            int row = lrow[it], seg = lseg[it];
            uint32_t d = swz(row, seg);
            size_t aoff = (size_t)(m0 + row) * K + k0 + seg * 8;
            cp16(s + d,              Ahp + aoff);
            cp16(s + TILE_B + d,     Alp + aoff);
            int brow = n0 + row; if (brow >= N) brow = N - 1;
            size_t boff = (size_t)brow * K + k0 + seg * 8;
            cp16(s + 2 * TILE_B + d, Bhp + boff);
            cp16(s + 3 * TILE_B + d, Blp + boff);
        }
        cp_commit();
    };

    float acc[4][4][4];
#pragma unroll
    for (int mi = 0; mi < 4; mi++)
#pragma unroll
        for (int ni = 0; ni < 4; ni++)
#pragma unroll
            for (int q = 0; q < 4; q++) acc[mi][ni][q] = 0.f;

    const int lgrp = lane >> 3, lr = lane & 7;
    const int a_roff = lr + (lgrp & 1) * 8;
    const int a_koff = lgrp >> 1;
    const int b_roff = lr + (lgrp >> 1) * 8;
    const int b_koff = lgrp & 1;

    // double-buffered fragments
    uint32_t ah[2][4][4], al[2][4][4], bh[2][4][2], bl[2][4][2];

    auto load_frags = [&](int buf, uint32_t s, int k16) {
        int k2 = k16 * 2;
#pragma unroll
        for (int mi = 0; mi < 4; mi++) {
            int row = wm * 64 + mi * 16 + a_roff;
            uint32_t ad = swz(row, k2 + a_koff);
            ldsm_x4(ah[buf][mi][0], ah[buf][mi][1], ah[buf][mi][2], ah[buf][mi][3], s + ad);
            ldsm_x4(al[buf][mi][0], al[buf][mi][1], al[buf][mi][2], al[buf][mi][3], s + TILE_B + ad);
        }
#pragma unroll
        for (int nj = 0; nj < 2; nj++) {
            int row = wn * 32 + nj * 16 + b_roff;
            uint32_t bd = swz(row, k2 + b_koff);
            uint32_t r0, r1, r2, r3;
            ldsm_x4(r0, r1, r2, r3, s + 2 * TILE_B + bd);
            bh[buf][nj * 2][0] = r0; bh[buf][nj * 2][1] = r1;
            bh[buf][nj * 2 + 1][0] = r2; bh[buf][nj * 2 + 1][1] = r3;
            ldsm_x4(r0, r1, r2, r3, s + 3 * TILE_B + bd);
            bl[buf][nj * 2][0] = r0; bl[buf][nj * 2][1] = r1;
            bl[buf][nj * 2 + 1][0] = r2; bl[buf][nj * 2 + 1][1] = r3;
        }
    };

    load_chunk(0, 0);
    load_chunk(1, KC);

    for (int c = 0; c < NC; c++) {
        if (c + 2 < NC) load_chunk((c + 2) % NSTAGE, (c + 2) * KC);
        else            cp_commit();                 // keep group count constant
        cp_wait<2>();                                // chunk c resident
        __syncthreads();

        uint32_t s = sb + (c % NSTAGE) * STAGE_B;
        load_frags(0, s, 0);
#pragma unroll
        for (int k16 = 0; k16 < 4; k16++) {
            if (k16 < 3) load_frags((k16 + 1) & 1, s, k16 + 1);  // prefetch next
            const int bb = k16 & 1;
#pragma unroll
            for (int mi = 0; mi < 4; mi++)
#pragma unroll
                for (int ni = 0; ni < 4; ni++) {
                    mma_bf16(acc[mi][ni], ah[bb][mi], bh[bb][ni][0], bh[bb][ni][1]);
                    mma_bf16(acc[mi][ni], ah[bb][mi], bl[bb][ni][0], bl[bb][ni][1]);
                    mma_bf16(acc[mi][ni], al[bb][mi], bh[bb][ni][0], bh[bb][ni][1]);
                }
        }
        __syncthreads();
    }

    // ---- epilogue ----
    const int quad = lane >> 2, qt = lane & 3;
#pragma unroll
    for (int mi = 0; mi < 4; mi++) {
#pragma unroll
        for (int ni = 0; ni < 4; ni++) {
            int gm = m0 + wm * 64 + mi * 16 + quad;
            int gn = n0 + wn * 32 + ni * 8 + qt * 2;
            if (gn < N) {
                {
                    float2 v = make_float2(acc[mi][ni][0], acc[mi][ni][1]);
                    size_t o = (size_t)gm * N + gn;
                    if (RES) { float2 rv = *(const float2*)(resid + o); v.x += rv.x; v.y += rv.y; }
                    *(float2*)(C + o) = v;
                }
                {
                    float2 v = make_float2(acc[mi][ni][2], acc[mi][ni][3]);
                    size_t o = (size_t)(gm + 8) * N + gn;
                    if (RES) { float2 rv = *(const float2*)(resid + o); v.x += rv.x; v.y += rv.y; }
                    *(float2*)(C + o) = v;
                }
            }
        }
    }
}

// =====================================================================
// merged fp32 -> bf16 hi/lo split for x, in_proj_w, out_proj_w (one launch)
// =====================================================================
#define N4_X  (ROWS*DMODEL/4)
#define N4_W1 (DINPROJ*DMODEL/4)
#define N4_W2 (DMODEL*DINNER/4)

__device__ __forceinline__ void split4(float4 v, __nv_bfloat162* hi, __nv_bfloat162* lo, int i) {
    __nv_bfloat16 hx = __float2bfloat16(v.x);
    __nv_bfloat16 hy = __float2bfloat16(v.y);
    __nv_bfloat16 hz = __float2bfloat16(v.z);
    __nv_bfloat16 hw = __float2bfloat16(v.w);
    hi[i * 2]     = __halves2bfloat162(hx, hy);
    hi[i * 2 + 1] = __halves2bfloat162(hz, hw);
    lo[i * 2]     = __halves2bfloat162(__float2bfloat16(v.x - __bfloat162float(hx)),
                                       __float2bfloat16(v.y - __bfloat162float(hy)));
    lo[i * 2 + 1] = __halves2bfloat162(__float2bfloat16(v.z - __bfloat162float(hz)),
                                       __float2bfloat16(v.w - __bfloat162float(hw)));
}

__global__ __launch_bounds__(256)
void cvt_all(const float4* __restrict__ x, const float4* __restrict__ w1,
             const float4* __restrict__ w2)
{
    int i = blockIdx.x * 256 + threadIdx.x;
    if (i < N4_X) {
        split4(x[i], (__nv_bfloat162*)g_xh, (__nv_bfloat162*)g_xl, i);
    } else if (i < N4_X + N4_W1) {
        int j = i - N4_X;
        split4(w1[j], (__nv_bfloat162*)g_w1h, (__nv_bfloat162*)g_w1l, j);
    } else if (i < N4_X + N4_W1 + N4_W2) {
        int j = i - N4_X - N4_W1;
        split4(w2[j], (__nv_bfloat162*)g_w2h, (__nv_bfloat162*)g_w2l, j);
    }
}

// =====================================================================
// Causal depthwise conv (width 4) + bias + SiLU; dt softplus; dA
// =====================================================================
__global__ __launch_bounds__(256)
void conv_act_kernel(const float* __restrict__ conv_w, const float* __restrict__ conv_b,
                     const float* __restrict__ dt_bias, const float* __restrict__ A_log)
{
    const int c  = blockIdx.x * 256 + threadIdx.x;   // < CONVDIM (grid.x = 9)
    const int tb = blockIdx.y * 4;
    const int b  = blockIdx.z;

    float w0 = conv_w[c * 4 + 0], w1 = conv_w[c * 4 + 1];
    float w2 = conv_w[c * 4 + 2], w3 = conv_w[c * 4 + 3];
    float bias = conv_b[c];

    float v[7];
#pragma unroll
    for (int k = 0; k < 7; k++) {
        int tt = tb - 3 + k;
        v[k] = (tt >= 0) ? g_zx[((size_t)b * SEQLEN + tt) * DINPROJ + DINNER + c] : 0.f;
    }
#pragma unroll
    for (int i = 0; i < 4; i++) {
        float a = bias + v[i] * w0 + v[i + 1] * w1 + v[i + 2] * w2 + v[i + 3] * w3;
        g_xbc[((size_t)b * SEQLEN + tb + i) * CONVDIM + c] = a / (1.f + expf(-a));
    }
    if (blockIdx.x == 0 && threadIdx.x < NHEADS) {
        int hh = threadIdx.x;
        float negA = -expf(A_log[hh]);
        float bth  = dt_bias[hh];
#pragma unroll
        for (int i = 0; i < 4; i++) {
            size_t row = (size_t)b * SEQLEN + tb + i;
            float raw = g_zx[row * DINPROJ + (DINNER + CONVDIM) + hh] + bth;
            float dtv = (raw > 20.f) ? raw : log1pf(expf(raw));
            g_dt[row * NHEADS + hh] = dtv;
            g_dA[row * NHEADS + hh] = expf(dtv * negA);
        }
    }
}

// =====================================================================
// Selective scan: grid (NHEADS, BATCH, 4 n-quarters) = 256 blocks.
// =====================================================================
__global__ __launch_bounds__(256)
void scan_kernel()
{
    const int h = blockIdx.x, b = blockIdx.y, q = blockIdx.z;
    const int tid = threadIdx.x;
    const int p = tid >> 2, ns = tid & 3;
    const int nbase = q * 32;
    float* __restrict__ yout = (q == 0) ? g_yp0 : (q == 1) ? g_yp1 : (q == 2) ? g_yp2 : g_yp3;

    __shared__ __align__(16) float sB[8][32];
    __shared__ __align__(16) float sC[8][32];
    __shared__ __align__(16) float sX[8][64];
    __shared__ float sdA[8], sdt[8];

    float2 hs[4];
#pragma unroll
    for (int j = 0; j < 4; j++) hs[j] = make_float2(0.f, 0.f);

    for (int t0 = 0; t0 < SEQLEN; t0 += 8) {
        __syncthreads();
        {
            int idx = tid;
            if (idx < 64) {
                int s = idx >> 3, f = idx & 7;
                size_t row = ((size_t)b * SEQLEN + t0 + s) * CONVDIM;
                *(float4*)&sB[s][f * 4] = *(const float4*)&g_xbc[row + DINNER + nbase + f * 4];
            } else if (idx < 128) {
                int r = idx - 64; int s = r >> 3, f = r & 7;
                size_t row = ((size_t)b * SEQLEN + t0 + s) * CONVDIM;
                *(float4*)&sC[s][f * 4] = *(const float4*)&g_xbc[row + DINNER + DSTATE + nbase + f * 4];
            } else {
                int r = idx - 128; int s = r >> 4, f = r & 15;
                size_t row = ((size_t)b * SEQLEN + t0 + s) * CONVDIM;
                *(float4*)&sX[s][f * 4] = *(const float4*)&g_xbc[row + h * HEADDIM + f * 4];
            }
            if (tid < 16) {
                int s = tid & 7;
                size_t r = ((size_t)b * SEQLEN + t0 + s) * NHEADS + h;
                if (tid < 8) sdA[s] = g_dA[r];
                else         sdt[s] = g_dt[r];
            }
        }
        __syncthreads();

#pragma unroll
        for (int s = 0; s < 8; s++) {
            float dAv = sdA[s];
            float2 dA2 = make_float2(dAv, dAv);
            float coef = sdt[s] * sX[s][p];
            float2 c2  = make_float2(coef, coef);
            float4 B0 = *(const float4*)&sB[s][ns * 4];
            float4 B1 = *(const float4*)&sB[s][ns * 4 + 16];
            float4 C0 = *(const float4*)&sC[s][ns * 4];
            float4 C1 = *(const float4*)&sC[s][ns * 4 + 16];
            float2 acc = make_float2(0.f, 0.f);
            hs[0] = ffma2(hs[0], dA2, fmul2(c2, make_float2(B0.x, B0.y)));
            acc   = ffma2(hs[0], make_float2(C0.x, C0.y), acc);
            hs[1] = ffma2(hs[1], dA2, fmul2(c2, make_float2(B0.z, B0.w)));
            acc   = ffma2(hs[1], make_float2(C0.z, C0.w), acc);
            hs[2] = ffma2(hs[2], dA2, fmul2(c2, make_float2(B1.x, B1.y)));
            acc   = ffma2(hs[2], make_float2(C1.x, C1.y), acc);
            hs[3] = ffma2(hs[3], dA2, fmul2(c2, make_float2(B1.z, B1.w)));
            acc   = ffma2(hs[3], make_float2(C1.z, C1.w), acc);
            float y = acc.x + acc.y;
            y += __shfl_down_sync(0xffffffffu, y, 2, 4);
            y += __shfl_down_sync(0xffffffffu, y, 1, 4);
            if (ns == 0)
                yout[((size_t)b * SEQLEN + t0 + s) * DINNER + h * HEADDIM + p] = y;
        }
    }
}

// =====================================================================
// skip + gate + RMSNorm -> bf16 hi/lo for GEMM2 (float4 vectorized)
// =====================================================================
__global__ __launch_bounds__(256)
void gate_norm_kernel(const float* __restrict__ Dw, const float* __restrict__ norm_w)
{
    const int t = blockIdx.x;
    const int b = blockIdx.y;
    const size_t row = (size_t)b * SEQLEN + t;
    const float4* __restrict__ z4 = (const float4*)&g_zx [row * DINPROJ];
    const float4* __restrict__ x4 = (const float4*)&g_xbc[row * CONVDIM];
    const float4* __restrict__ y0 = (const float4*)&g_yp0[row * DINNER];
    const float4* __restrict__ y1 = (const float4*)&g_yp1[row * DINNER];
    const float4* __restrict__ y2 = (const float4*)&g_yp2[row * DINNER];
    const float4* __restrict__ y3 = (const float4*)&g_yp3[row * DINNER];

    float4 vals[2];
    float ss = 0.f;
#pragma unroll
    for (int r = 0; r < 2; r++) {
        int f = r * 256 + threadIdx.x;          // float4 index in [0,512)
        float dv = Dw[f >> 4];
        float4 a = y0[f], bq = y1[f], cq = y2[f], dq = y3[f], xv = x4[f], zv = z4[f];
        float4 v;
        v.x = a.x + bq.x + cq.x + dq.x + dv * xv.x;
        v.y = a.y + bq.y + cq.y + dq.y + dv * xv.y;
        v.z = a.z + bq.z + cq.z + dq.z + dv * xv.z;
        v.w = a.w + bq.w + cq.w + dq.w + dv * xv.w;
        v.x *= zv.x / (1.f + expf(-zv.x));
        v.y *= zv.y / (1.f + expf(-zv.y));
        v.z *= zv.z / (1.f + expf(-zv.z));
        v.w *= zv.w / (1.f + expf(-zv.w));
        vals[r] = v;
        ss += v.x * v.x + v.y * v.y + v.z * v.z + v.w * v.w;
    }
    __shared__ float red[256];
    red[threadIdx.x] = ss;
    __syncthreads();
    for (int off = 128; off > 0; off >>= 1) {
        if (threadIdx.x < off) red[threadIdx.x] += red[threadIdx.x + off];
        __syncthreads();
    }
    float scale = rsqrtf(red[0] / (float)DINNER + EPS);
    __nv_bfloat162* outh = (__nv_bfloat162*)&g_ynh[row * DINNER];
    __nv_bfloat162* outl = (__nv_bfloat162*)&g_ynl[row * DINNER];
    const float4* nw4 = (const float4*)norm_w;
#pragma unroll
    for (int r = 0; r < 2; r++) {
        int f = r * 256 + threadIdx.x;
        float4 w = nw4[f];
        float4 v = vals[r];
        v.x *= scale * w.x; v.y *= scale * w.y; v.z *= scale * w.z; v.w *= scale * w.w;
        split4(v, outh, outl, f);
    }
}

// =====================================================================
extern "C" void kernel_launch(void* const* d_in, const int* in_sizes, int n_in,
                              void* d_out, int out_size)
{
    const float* x          = (const float*)d_in[0];
    const float* in_proj_w  = (const float*)d_in[1];
    const float* conv_w     = (const float*)d_in[2];
    const float* conv_b     = (const float*)d_in[3];
    const float* dt_bias    = (const float*)d_in[4];
    const float* A_log      = (const float*)d_in[5];
    const float* Dw         = (const float*)d_in[6];
    const float* norm_w     = (const float*)d_in[7];
    const float* out_proj_w = (const float*)d_in[8];
    float* out = (float*)d_out;

    float *p_zx = nullptr;
    void *p_xh, *p_xl, *p_w1h, *p_w1l, *p_w2h, *p_w2l, *p_ynh, *p_ynl;
    cudaGetSymbolAddress((void**)&p_zx, g_zx);
    cudaGetSymbolAddress(&p_xh,  g_xh);  cudaGetSymbolAddress(&p_xl,  g_xl);
    cudaGetSymbolAddress(&p_w1h, g_w1h); cudaGetSymbolAddress(&p_w1l, g_w1l);
    cudaGetSymbolAddress(&p_w2h, g_w2h); cudaGetSymbolAddress(&p_w2l, g_w2l);
    cudaGetSymbolAddress(&p_ynh, g_ynh); cudaGetSymbolAddress(&p_ynl, g_ynl);

    cudaFuncSetAttribute(gemm_mma<false>, cudaFuncAttributeMaxDynamicSharedMemorySize, SMEM_GEMM);
    cudaFuncSetAttribute(gemm_mma<true>,  cudaFuncAttributeMaxDynamicSharedMemorySize, SMEM_GEMM);

    // 0) fp32 -> bf16 hi/lo conversions (one merged launch)
    {
        int total4 = N4_X + N4_W1 + N4_W2;
        cvt_all<<<(total4 + 255)/256, 256>>>(
            (const float4*)x, (const float4*)in_proj_w, (const float4*)out_proj_w);
    }

    // 1) zxbcdt = x @ in_proj_w^T   [2048 x 4384]
    gemm_mma<false><<<dim3((DINPROJ + BN - 1)/BN, ROWS/BM), 256, SMEM_GEMM>>>(
        (const __nv_bfloat16*)p_xh, (const __nv_bfloat16*)p_xl,
        (const __nv_bfloat16*)p_w1h, (const __nv_bfloat16*)p_w1l,
        nullptr, p_zx, DINPROJ, DMODEL);

    // 2) conv + SiLU; dt/dA
    conv_act_kernel<<<dim3(CONVDIM/256, SEQLEN/4, BATCH), 256>>>(conv_w, conv_b, dt_bias, A_log);

    // 3) selective scan (4 state-quarters)
    scan_kernel<<<dim3(NHEADS, BATCH, 4), 256>>>();

    // 4) skip + gate + RMSNorm (emits bf16 hi/lo)
    gate_norm_kernel<<<dim3(SEQLEN, BATCH), 256>>>(Dw, norm_w);

    // 5) out = x + yn @ out_proj_w^T   [2048 x 1024]
    gemm_mma<true><<<dim3(DMODEL/BN, ROWS/BM), 256, SMEM_GEMM>>>(
        (const __nv_bfloat16*)p_ynh, (const __nv_bfloat16*)p_ynl,
        (const __nv_bfloat16*)p_w2h, (const __nv_bfloat16*)p_w2l,
        x, out, DMODEL, DINNER);
}